// round 14
// baseline (speedup 1.0000x reference)
#include <cuda_runtime.h>
#include <cuda_bf16.h>
#include <math.h>
#include <stdint.h>

// Problem constants
#define NTOK   8192      // B*T
#define DMODEL 1024
#define DFFN   4096
#define NEXP   8
#define NSLOT  (NTOK*2)

// GEMM tiling: CTA 128x256x32, 16 warps (4M x 4N), warp tile 32x64
#define TILE_M 128
#define TILE_N 256
#define TILE_K 32
#define NTHREADS 512
// per stage: A_hi[128x64B] A_lo[128x64B] B_hi[32x512B] B_lo[32x512B] = 48KB
#define A_HI 0
#define A_LO 8192
#define B_HI 16384
#define B_LO 32768
#define STAGE_BYTES 49152
#define SMEM_TOTAL  (2 * STAGE_BYTES)    // 96KB dynamic

// ---------------- device scratch (no cudaMalloc allowed; 320MB envelope) --------
__device__ float g_h[(size_t)NSLOT * DFFN];     // 256 MB fp32 intermediate
__device__ float g_yp[(size_t)NSLOT * DMODEL];  // 64 MB
__device__ int   g_expert_count[NEXP];
__device__ int   g_expert_slots[NEXP][NTOK];
__device__ float g_slot_w[NSLOT];
__device__ float g_imp_sum[NEXP];
__device__ float g_z2_sum;

// ---------------- helpers ----------------
__device__ __forceinline__ uint32_t smem_to_u32(const void* smem_ptr) {
    uint32_t addr;
    asm("{ .reg .u64 tmp; cvta.to.shared.u64 tmp, %1; cvt.u32.u64 %0, tmp; }"
        : "=r"(addr) : "l"(smem_ptr));
    return addr;
}

__device__ __forceinline__ void ldm_x4(uint32_t* r, uint32_t addr) {
    asm volatile("ldmatrix.sync.aligned.m8n8.x4.shared.b16 {%0,%1,%2,%3}, [%4];"
        : "=r"(r[0]), "=r"(r[1]), "=r"(r[2]), "=r"(r[3]) : "r"(addr));
}

__device__ __forceinline__ void ldm_x4_trans(uint32_t* r, uint32_t addr) {
    asm volatile("ldmatrix.sync.aligned.m8n8.x4.trans.shared.b16 {%0,%1,%2,%3}, [%4];"
        : "=r"(r[0]), "=r"(r[1]), "=r"(r[2]), "=r"(r[3]) : "r"(addr));
}

__device__ __forceinline__ void mma_bf16(float* c, const uint32_t* a,
                                         uint32_t b0, uint32_t b1) {
    asm volatile(
        "mma.sync.aligned.m16n8k16.row.col.f32.bf16.bf16.f32 "
        "{%0,%1,%2,%3}, {%4,%5,%6,%7}, {%8,%9}, {%0,%1,%2,%3};"
        : "+f"(c[0]), "+f"(c[1]), "+f"(c[2]), "+f"(c[3])
        : "r"(a[0]), "r"(a[1]), "r"(a[2]), "r"(a[3]), "r"(b0), "r"(b1));
}

__device__ __forceinline__ void split_bf16(float v, __nv_bfloat16& hi, __nv_bfloat16& lo) {
    hi = __float2bfloat16_rn(v);
    lo = __float2bfloat16_rn(v - __bfloat162float(hi));
}

// split 8 fp32 -> uint4 of 8 bf16 hi + uint4 of 8 bf16 lo (element order preserved)
__device__ __forceinline__ void split8(float4 a, float4 b, uint4& hi, uint4& lo) {
    float v[8] = {a.x, a.y, a.z, a.w, b.x, b.y, b.z, b.w};
    uint32_t h[4], l[4];
    #pragma unroll
    for (int p = 0; p < 4; p++) {
        __nv_bfloat16 h0, l0, h1, l1;
        split_bf16(v[2*p],   h0, l0);
        split_bf16(v[2*p+1], h1, l1);
        __nv_bfloat162 hh; hh.x = h0; hh.y = h1;
        __nv_bfloat162 ll; ll.x = l0; ll.y = l1;
        h[p] = *(uint32_t*)&hh;
        l[p] = *(uint32_t*)&ll;
    }
    hi = make_uint4(h[0], h[1], h[2], h[3]);
    lo = make_uint4(l[0], l[1], l[2], l[3]);
}

// ---------------- kernel 0: zero accumulators ----------------
__global__ void zero_kernel() {
    int t = threadIdx.x;
    if (t < NEXP) { g_expert_count[t] = 0; g_imp_sum[t] = 0.f; }
    if (t == 0)   g_z2_sum = 0.f;
}

// ---------------- kernel 1: router (one block per token) ----------------
__global__ __launch_bounds__(128) void router_kernel(
    const float* __restrict__ x, const float* __restrict__ Wr)
{
    const int t = blockIdx.x;
    const int tid = threadIdx.x;
    const float* xr = x + (size_t)t * DMODEL;

    float acc[NEXP];
    #pragma unroll
    for (int e = 0; e < NEXP; e++) acc[e] = 0.f;

    for (int d = tid; d < DMODEL; d += 128) {
        float xv = xr[d];
        const float4* w4 = (const float4*)(Wr + (size_t)d * NEXP);
        float4 wa = w4[0], wb = w4[1];
        acc[0] += xv * wa.x; acc[1] += xv * wa.y;
        acc[2] += xv * wa.z; acc[3] += xv * wa.w;
        acc[4] += xv * wb.x; acc[5] += xv * wb.y;
        acc[6] += xv * wb.z; acc[7] += xv * wb.w;
    }

    __shared__ float s[NEXP][128];
    #pragma unroll
    for (int e = 0; e < NEXP; e++) s[e][tid] = acc[e];
    __syncthreads();
    for (int off = 64; off > 0; off >>= 1) {
        if (tid < off) {
            #pragma unroll
            for (int e = 0; e < NEXP; e++) s[e][tid] += s[e][tid + off];
        }
        __syncthreads();
    }

    if (tid == 0) {
        float lg[NEXP];
        #pragma unroll
        for (int e = 0; e < NEXP; e++) lg[e] = s[e][0];

        float mx = lg[0];
        #pragma unroll
        for (int e = 1; e < NEXP; e++) mx = fmaxf(mx, lg[e]);
        float ex[NEXP], ps = 0.f;
        #pragma unroll
        for (int e = 0; e < NEXP; e++) { ex[e] = expf(lg[e] - mx); ps += ex[e]; }
        float inv = 1.f / ps;
        #pragma unroll
        for (int e = 0; e < NEXP; e++) atomicAdd(&g_imp_sum[e], ex[e] * inv);
        float z = mx + logf(ps);
        atomicAdd(&g_z2_sum, z * z);

        int i0 = 0; float v0 = lg[0];
        #pragma unroll
        for (int e = 1; e < NEXP; e++) if (lg[e] > v0) { v0 = lg[e]; i0 = e; }
        int i1 = -1; float v1 = -1e30f;
        #pragma unroll
        for (int e = 0; e < NEXP; e++) {
            if (e == i0) continue;
            if (lg[e] > v1) { v1 = lg[e]; i1 = e; }
        }
        float r = expf(v1 - v0);
        float w0 = 1.f / (1.f + r);
        float w1 = r / (1.f + r);

        int slot0 = t * 2, slot1 = t * 2 + 1;
        g_slot_w[slot0] = w0;
        g_slot_w[slot1] = w1;
        int p0 = atomicAdd(&g_expert_count[i0], 1);
        g_expert_slots[i0][p0] = slot0;
        int p1 = atomicAdd(&g_expert_count[i1], 1);
        g_expert_slots[i1][p1] = slot1;
    }
}

// ---------------- HMMA GEMM (mma.sync bf16, hi/lo split = 3 MMAs) ----------
// 16 warps (4 warps/SMSP) for issue-slack; warp tile 32x64; CTA 128x256.
// MODE 1: A = x fp32 (row = slot>>1), B = W1[e] [d][f], K=1024, N=4096 -> g_h
// MODE 2: A = g_h   (row = slot),     B = W2[e] [f][d], K=4096, N=1024 -> g_yp

template<int MODE>
__global__ __launch_bounds__(NTHREADS) void moe_gemm_mma(
    const float* __restrict__ Aext, const float* __restrict__ Bg,
    const float* __restrict__ biasg)
{
    constexpr int NDIM = (MODE == 1) ? DFFN : DMODEL;
    constexpr int KDIM = (MODE == 1) ? DMODEL : DFFN;
    constexpr int NT   = KDIM / TILE_K;

    const int e = blockIdx.z;
    const int count = g_expert_count[e];
    const int m0 = blockIdx.y * TILE_M;
    if (m0 >= count) return;
    const int n0 = blockIdx.x * TILE_N;

    const int* slots = g_expert_slots[e];
    const float* A = (MODE == 1) ? Aext : (const float*)g_h;
    const float* B = Bg + (size_t)e * KDIM * NDIM;   // [k][n] row-major
    const float* bias = biasg + (size_t)e * NDIM;

    extern __shared__ __align__(128) char smbuf[];
    const uint32_t smA = smem_to_u32(smbuf);

    const int tid = threadIdx.x;
    const int wid = tid >> 5, lane = tid & 31;
    const int wm = wid >> 2;          // 0..3 : warp M block (32 rows)
    const int wn = wid & 3;           // 0..3 : warp N block (64 cols)

    // ---- per-thread fill assignment: 1 A source chunk + 2 B source chunks ----
    // source chunk = 8 consecutive fp32 (32B) -> 16B hi + 16B lo in smem
    const float* pA; const float* pB[2];
    uint32_t offA, offB[2];
    {
        int rA = tid >> 2, cA = tid & 3;          // 128 rows x 4 chunks = 512
        offA = (uint32_t)(rA * 64 + ((cA ^ ((rA >> 1) & 3)) * 16));
        int gm = m0 + rA;
        if (gm < count) {
            int slot = slots[gm];
            int row = (MODE == 1) ? (slot >> 1) : slot;
            pA = A + (size_t)row * KDIM + cA * 8;
        } else pA = nullptr;
    }
    #pragma unroll
    for (int s = 0; s < 2; s++) {
        int idx = tid + s * NTHREADS;             // 32 k-rows x 32 chunks = 1024
        int kB = idx >> 5, cB = idx & 31;
        offB[s] = (uint32_t)(kB * 512 + ((cB ^ (kB & 7)) * 16));
        pB[s] = B + (size_t)kB * NDIM + n0 + cB * 8;
    }

    float4 fa[2], fb[2][2];
    const float4 FZ = make_float4(0.f, 0.f, 0.f, 0.f);

    auto loadT = [&](int kt) {
        const int k0 = kt * TILE_K;
        if (pA) {
            fa[0] = *(const float4*)(pA + k0);
            fa[1] = *(const float4*)(pA + k0 + 4);
        } else { fa[0] = FZ; fa[1] = FZ; }
        const size_t bo = (size_t)k0 * NDIM;
        #pragma unroll
        for (int s = 0; s < 2; s++) {
            const float* bp = pB[s] + bo;
            fb[s][0] = *(const float4*)(bp);
            fb[s][1] = *(const float4*)(bp + 4);
        }
    };
    auto storeT = [&](int buf) {
        char* sb = smbuf + buf * STAGE_BYTES;
        uint4 hi, lo;
        split8(fa[0], fa[1], hi, lo);
        *(uint4*)(sb + A_HI + offA) = hi;
        *(uint4*)(sb + A_LO + offA) = lo;
        #pragma unroll
        for (int s = 0; s < 2; s++) {
            split8(fb[s][0], fb[s][1], hi, lo);
            *(uint4*)(sb + B_HI + offB[s]) = hi;
            *(uint4*)(sb + B_LO + offB[s]) = lo;
        }
    };

    float acc[2][8][4];
    #pragma unroll
    for (int i = 0; i < 2; i++)
        #pragma unroll
        for (int j = 0; j < 8; j++)
            #pragma unroll
            for (int q = 0; q < 4; q++) acc[i][j][q] = 0.f;

    // ---- ldmatrix lane addressing (swizzle-aware) ----
    const int a_row = wm * 32 + (lane & 15);
    const int a_ch  = lane >> 4;
    const int ka    = (a_row >> 1) & 3;   // invariant under +16*mt
    uint32_t aoff[2];
    const int b_k  = (lane & 7) + (((lane >> 3) & 1) << 3);
    const int b_ch = lane >> 4;
    const int bswz = lane & 7;            // = (s*16+b_k)&7
    uint32_t boff[2][4];
    #pragma unroll
    for (int s = 0; s < 2; s++) {
        aoff[s] = (uint32_t)(a_row * 64 + (((s * 2 + a_ch) ^ ka) * 16));
        #pragma unroll
        for (int bt = 0; bt < 4; bt++)
            boff[s][bt] = (uint32_t)((s * 16 + b_k) * 512
                          + (((wn * 8 + bt * 2 + b_ch) ^ bswz) * 16));
    }

    loadT(0); storeT(0);
    __syncthreads();

    for (int kt = 0; kt < NT; kt++) {
        const uint32_t base = smA + (uint32_t)(kt & 1) * STAGE_BYTES;
        if (kt + 1 < NT) loadT(kt + 1);

        #pragma unroll
        for (int s = 0; s < 2; s++) {               // two k16 slabs
            uint32_t ah[2][4], al[2][4];
            #pragma unroll
            for (int mt = 0; mt < 2; mt++) {
                ldm_x4(ah[mt], base + A_HI + aoff[s] + mt * 1024);
                ldm_x4(al[mt], base + A_LO + aoff[s] + mt * 1024);
            }
            #pragma unroll
            for (int bt = 0; bt < 4; bt++) {        // B fragments on the fly
                uint32_t bh[4], bl[4];
                ldm_x4_trans(bh, base + B_HI + boff[s][bt]);
                ldm_x4_trans(bl, base + B_LO + boff[s][bt]);
                #pragma unroll
                for (int mt = 0; mt < 2; mt++)
                    #pragma unroll
                    for (int jj = 0; jj < 2; jj++) {
                        const int j = bt * 2 + jj, p = jj * 2;
                        mma_bf16(acc[mt][j], ah[mt], bh[p], bh[p + 1]);
                        mma_bf16(acc[mt][j], ah[mt], bl[p], bl[p + 1]);
                        mma_bf16(acc[mt][j], al[mt], bh[p], bh[p + 1]);
                    }
            }
        }
        if (kt + 1 < NT) storeT((kt + 1) & 1);   // disjoint buffer: overlaps HMMA
        __syncthreads();
    }

    // ---- epilogue straight from fragments ----
    const int col_in = wn * 64 + (lane & 3) * 2;
    #pragma unroll
    for (int mt = 0; mt < 2; mt++) {
        #pragma unroll
        for (int g = 0; g < 2; g++) {
            const int gm = m0 + wm * 32 + mt * 16 + (lane >> 2) + g * 8;
            if (gm >= count) continue;
            const int slot = slots[gm];
            if (MODE == 1) {
                #pragma unroll
                for (int j = 0; j < 8; j++) {
                    const int col = n0 + col_in + j * 8;
                    float2 bb = *(const float2*)(bias + col);
                    float2 o;
                    o.x = fmaxf(acc[mt][j][g * 2 + 0] + bb.x, 0.f);
                    o.y = fmaxf(acc[mt][j][g * 2 + 1] + bb.y, 0.f);
                    *(float2*)&g_h[(size_t)slot * DFFN + col] = o;
                }
            } else {
                const float wgt = g_slot_w[slot];
                #pragma unroll
                for (int j = 0; j < 8; j++) {
                    const int col = n0 + col_in + j * 8;
                    float2 bb = *(const float2*)(bias + col);
                    float2 o;
                    o.x = (acc[mt][j][g * 2 + 0] + bb.x) * wgt;
                    o.y = (acc[mt][j][g * 2 + 1] + bb.y) * wgt;
                    *(float2*)&g_yp[(size_t)slot * DMODEL + col] = o;
                }
            }
        }
    }
}

// ---------------- combine: y[t] = yp[2t] + yp[2t+1] ----------------
__global__ __launch_bounds__(256) void combine_kernel(float* __restrict__ y)
{
    int i = blockIdx.x * blockDim.x + threadIdx.x;
    int t = i >> 8;
    int d4 = i & 255;
    const float4* yp = (const float4*)g_yp;
    float4 a = yp[(size_t)(2 * t) * 256 + d4];
    float4 b = yp[(size_t)(2 * t + 1) * 256 + d4];
    ((float4*)y)[(size_t)t * 256 + d4] =
        make_float4(a.x + b.x, a.y + b.y, a.z + b.z, a.w + b.w);
}

// ---------------- finalize: counts / fraction / aux_loss ----------------
__global__ void finalize_kernel(float* __restrict__ out)
{
    if (threadIdx.x != 0) return;
    const size_t Y = (size_t)NTOK * DMODEL;
    float total = 0.f;
    float c[NEXP];
    #pragma unroll
    for (int e = 0; e < NEXP; e++) { c[e] = (float)g_expert_count[e]; total += c[e]; }
    float denom = fmaxf(total, 1.f);
    float lb = 0.f;
    #pragma unroll
    for (int e = 0; e < NEXP; e++) {
        out[Y + e] = c[e];
        out[Y + NEXP + e] = c[e] / denom;
        float imp = g_imp_sum[e] / (float)NTOK;
        lb += imp * imp;
    }
    float lb_loss = (float)NEXP * lb * 0.01f;
    float z_loss  = (g_z2_sum / (float)NTOK) * 0.001f;
    out[Y + 2 * NEXP] = lb_loss + z_loss;
}

// ---------------- launch ----------------
extern "C" void kernel_launch(void* const* d_in, const int* in_sizes, int n_in,
                              void* d_out, int out_size)
{
    const float* x  = (const float*)d_in[0];
    const float* Wr = (const float*)d_in[1];
    const float* W1 = (const float*)d_in[2];
    const float* b1 = (const float*)d_in[3];
    const float* W2 = (const float*)d_in[4];
    const float* b2 = (const float*)d_in[5];
    float* out = (float*)d_out;

    cudaFuncSetAttribute(moe_gemm_mma<1>,
                         cudaFuncAttributeMaxDynamicSharedMemorySize, SMEM_TOTAL);
    cudaFuncSetAttribute(moe_gemm_mma<2>,
                         cudaFuncAttributeMaxDynamicSharedMemorySize, SMEM_TOTAL);

    zero_kernel<<<1, 32>>>();
    router_kernel<<<NTOK, 128>>>(x, Wr);

    // GEMM1: per-expert M<=8192, N=4096, K=1024 (B = W1[e] in [d][f] layout)
    moe_gemm_mma<1><<<dim3(DFFN / TILE_N, NTOK / TILE_M, NEXP), NTHREADS, SMEM_TOTAL>>>(x, W1, b1);
    // GEMM2: per-expert M<=8192, N=1024, K=4096 (B = W2[e] in [f][d] layout)
    moe_gemm_mma<2><<<dim3(DMODEL / TILE_N, NTOK / TILE_M, NEXP), NTHREADS, SMEM_TOTAL>>>(nullptr, W2, b2);

    combine_kernel<<<(NTOK * 256) / 256, 256>>>(out);
    finalize_kernel<<<1, 32>>>(out);
}

// round 15
// speedup vs baseline: 3.0326x; 3.0326x over previous
#include <cuda_runtime.h>
#include <cuda_bf16.h>
#include <cuda_fp16.h>
#include <math.h>
#include <stdint.h>

// Problem constants
#define NTOK   8192      // B*T
#define DMODEL 1024
#define DFFN   4096
#define NEXP   8
#define NSLOT  (NTOK*2)

// GEMM tiling: CTA 128x256x32, 8 warps (2M x 4N), warp tile 64x64 (R13 shape)
#define TILE_M 128
#define TILE_N 256
#define TILE_K 32
// per stage: A[128x64B] B[32x512B] = 24KB (single fp16 operand, no hi/lo)
#define A_F16 0
#define B_F16 8192
#define STAGE_BYTES 24576
#define SMEM_TOTAL  (2 * STAGE_BYTES)    // 48KB dynamic

// ---------------- device scratch (no cudaMalloc allowed; 320MB envelope) --------
__device__ float g_h[(size_t)NSLOT * DFFN];     // 256 MB fp32 intermediate
__device__ float g_yp[(size_t)NSLOT * DMODEL];  // 64 MB
__device__ int   g_expert_count[NEXP];
__device__ int   g_expert_slots[NEXP][NTOK];
__device__ float g_slot_w[NSLOT];
__device__ float g_imp_sum[NEXP];
__device__ float g_z2_sum;

// ---------------- helpers ----------------
__device__ __forceinline__ uint32_t smem_to_u32(const void* smem_ptr) {
    uint32_t addr;
    asm("{ .reg .u64 tmp; cvta.to.shared.u64 tmp, %1; cvt.u32.u64 %0, tmp; }"
        : "=r"(addr) : "l"(smem_ptr));
    return addr;
}

__device__ __forceinline__ void ldm_x4(uint32_t* r, uint32_t addr) {
    asm volatile("ldmatrix.sync.aligned.m8n8.x4.shared.b16 {%0,%1,%2,%3}, [%4];"
        : "=r"(r[0]), "=r"(r[1]), "=r"(r[2]), "=r"(r[3]) : "r"(addr));
}

__device__ __forceinline__ void ldm_x4_trans(uint32_t* r, uint32_t addr) {
    asm volatile("ldmatrix.sync.aligned.m8n8.x4.trans.shared.b16 {%0,%1,%2,%3}, [%4];"
        : "=r"(r[0]), "=r"(r[1]), "=r"(r[2]), "=r"(r[3]) : "r"(addr));
}

__device__ __forceinline__ void mma_fp16(float* c, const uint32_t* a,
                                         uint32_t b0, uint32_t b1) {
    asm volatile(
        "mma.sync.aligned.m16n8k16.row.col.f32.f16.f16.f32 "
        "{%0,%1,%2,%3}, {%4,%5,%6,%7}, {%8,%9}, {%0,%1,%2,%3};"
        : "+f"(c[0]), "+f"(c[1]), "+f"(c[2]), "+f"(c[3])
        : "r"(a[0]), "r"(a[1]), "r"(a[2]), "r"(a[3]), "r"(b0), "r"(b1));
}

// convert 8 fp32 -> uint4 of 8 fp16 (element order preserved)
__device__ __forceinline__ uint4 conv8(float4 a, float4 b) {
    __half2 h0 = __floats2half2_rn(a.x, a.y);
    __half2 h1 = __floats2half2_rn(a.z, a.w);
    __half2 h2 = __floats2half2_rn(b.x, b.y);
    __half2 h3 = __floats2half2_rn(b.z, b.w);
    return make_uint4(*(uint32_t*)&h0, *(uint32_t*)&h1,
                      *(uint32_t*)&h2, *(uint32_t*)&h3);
}

// ---------------- kernel 0: zero accumulators ----------------
__global__ void zero_kernel() {
    int t = threadIdx.x;
    if (t < NEXP) { g_expert_count[t] = 0; g_imp_sum[t] = 0.f; }
    if (t == 0)   g_z2_sum = 0.f;
}

// ---------------- kernel 1: router (one block per token) ----------------
__global__ __launch_bounds__(128) void router_kernel(
    const float* __restrict__ x, const float* __restrict__ Wr)
{
    const int t = blockIdx.x;
    const int tid = threadIdx.x;
    const float* xr = x + (size_t)t * DMODEL;

    float acc[NEXP];
    #pragma unroll
    for (int e = 0; e < NEXP; e++) acc[e] = 0.f;

    for (int d = tid; d < DMODEL; d += 128) {
        float xv = xr[d];
        const float4* w4 = (const float4*)(Wr + (size_t)d * NEXP);
        float4 wa = w4[0], wb = w4[1];
        acc[0] += xv * wa.x; acc[1] += xv * wa.y;
        acc[2] += xv * wa.z; acc[3] += xv * wa.w;
        acc[4] += xv * wb.x; acc[5] += xv * wb.y;
        acc[6] += xv * wb.z; acc[7] += xv * wb.w;
    }

    __shared__ float s[NEXP][128];
    #pragma unroll
    for (int e = 0; e < NEXP; e++) s[e][tid] = acc[e];
    __syncthreads();
    for (int off = 64; off > 0; off >>= 1) {
        if (tid < off) {
            #pragma unroll
            for (int e = 0; e < NEXP; e++) s[e][tid] += s[e][tid + off];
        }
        __syncthreads();
    }

    if (tid == 0) {
        float lg[NEXP];
        #pragma unroll
        for (int e = 0; e < NEXP; e++) lg[e] = s[e][0];

        float mx = lg[0];
        #pragma unroll
        for (int e = 1; e < NEXP; e++) mx = fmaxf(mx, lg[e]);
        float ex[NEXP], ps = 0.f;
        #pragma unroll
        for (int e = 0; e < NEXP; e++) { ex[e] = expf(lg[e] - mx); ps += ex[e]; }
        float inv = 1.f / ps;
        #pragma unroll
        for (int e = 0; e < NEXP; e++) atomicAdd(&g_imp_sum[e], ex[e] * inv);
        float z = mx + logf(ps);
        atomicAdd(&g_z2_sum, z * z);

        int i0 = 0; float v0 = lg[0];
        #pragma unroll
        for (int e = 1; e < NEXP; e++) if (lg[e] > v0) { v0 = lg[e]; i0 = e; }
        int i1 = -1; float v1 = -1e30f;
        #pragma unroll
        for (int e = 0; e < NEXP; e++) {
            if (e == i0) continue;
            if (lg[e] > v1) { v1 = lg[e]; i1 = e; }
        }
        float r = expf(v1 - v0);
        float w0 = 1.f / (1.f + r);
        float w1 = r / (1.f + r);

        int slot0 = t * 2, slot1 = t * 2 + 1;
        g_slot_w[slot0] = w0;
        g_slot_w[slot1] = w1;
        int p0 = atomicAdd(&g_expert_count[i0], 1);
        g_expert_slots[i0][p0] = slot0;
        int p1 = atomicAdd(&g_expert_count[i1], 1);
        g_expert_slots[i1][p1] = slot1;
    }
}

// ---------------- HMMA GEMM (mma.sync fp16, single MMA, fp32 accum) --------
// fp16 quantization: per-product rel err ~2^-12; output rel err ~2-3e-4 per GEMM
// (threshold 1e-3). Tensor work is 1/3 of the bf16 hi/lo scheme.
// MODE 1: A = x fp32 (row = slot>>1), B = W1[e] [d][f], K=1024, N=4096 -> g_h
// MODE 2: A = g_h   (row = slot),     B = W2[e] [f][d], K=4096, N=1024 -> g_yp

template<int MODE>
__global__ __launch_bounds__(256) void moe_gemm_mma(
    const float* __restrict__ Aext, const float* __restrict__ Bg,
    const float* __restrict__ biasg)
{
    constexpr int NDIM = (MODE == 1) ? DFFN : DMODEL;
    constexpr int KDIM = (MODE == 1) ? DMODEL : DFFN;
    constexpr int NT   = KDIM / TILE_K;

    const int e = blockIdx.z;
    const int count = g_expert_count[e];
    const int m0 = blockIdx.y * TILE_M;
    if (m0 >= count) return;
    const int n0 = blockIdx.x * TILE_N;

    const int* slots = g_expert_slots[e];
    const float* A = (MODE == 1) ? Aext : (const float*)g_h;
    const float* B = Bg + (size_t)e * KDIM * NDIM;   // [k][n] row-major
    const float* bias = biasg + (size_t)e * NDIM;

    extern __shared__ __align__(128) char smbuf[];
    const uint32_t smA = smem_to_u32(smbuf);

    const int tid = threadIdx.x;
    const int wid = tid >> 5, lane = tid & 31;
    const int wm = wid >> 2;          // 0..1 : warp M block (64 rows)
    const int wn = wid & 3;           // 0..3 : warp N block (64 cols)

    // ---- per-thread fill assignment: 2 A source chunks + 4 B source chunks ----
    // source chunk = 8 consecutive fp32 (32B) -> 16B fp16 in smem
    const float* pA[2]; const float* pB[4];
    uint32_t offA[2], offB[4];
    #pragma unroll
    for (int s = 0; s < 2; s++) {
        int idx = tid + s * 256;          // 0..511 over 128 rows x 4 chunks
        int rA = idx >> 2, cA = idx & 3;
        offA[s] = (uint32_t)(rA * 64 + ((cA ^ ((rA >> 1) & 3)) * 16));
        int gm = m0 + rA;
        if (gm < count) {
            int slot = slots[gm];
            int row = (MODE == 1) ? (slot >> 1) : slot;
            pA[s] = A + (size_t)row * KDIM + cA * 8;
        } else pA[s] = nullptr;
    }
    #pragma unroll
    for (int s = 0; s < 4; s++) {
        int idx = tid + s * 256;          // 0..1023 over 32 k-rows x 32 chunks
        int kB = idx >> 5, cB = idx & 31;
        offB[s] = (uint32_t)(kB * 512 + ((cB ^ (kB & 7)) * 16));
        pB[s] = B + (size_t)kB * NDIM + n0 + cB * 8;
    }

    float4 fa[2][2], fb[4][2];
    const float4 FZ = make_float4(0.f, 0.f, 0.f, 0.f);

    auto loadT = [&](int kt) {
        const int k0 = kt * TILE_K;
        #pragma unroll
        for (int s = 0; s < 2; s++) {
            if (pA[s]) {
                fa[s][0] = *(const float4*)(pA[s] + k0);
                fa[s][1] = *(const float4*)(pA[s] + k0 + 4);
            } else { fa[s][0] = FZ; fa[s][1] = FZ; }
        }
        const size_t bo = (size_t)k0 * NDIM;
        #pragma unroll
        for (int s = 0; s < 4; s++) {
            const float* bp = pB[s] + bo;
            fb[s][0] = *(const float4*)(bp);
            fb[s][1] = *(const float4*)(bp + 4);
        }
    };
    auto storeT = [&](int buf) {
        char* sb = smbuf + buf * STAGE_BYTES;
        #pragma unroll
        for (int s = 0; s < 2; s++)
            *(uint4*)(sb + A_F16 + offA[s]) = conv8(fa[s][0], fa[s][1]);
        #pragma unroll
        for (int s = 0; s < 4; s++)
            *(uint4*)(sb + B_F16 + offB[s]) = conv8(fb[s][0], fb[s][1]);
    };

    float acc[4][8][4];
    #pragma unroll
    for (int i = 0; i < 4; i++)
        #pragma unroll
        for (int j = 0; j < 8; j++)
            #pragma unroll
            for (int q = 0; q < 4; q++) acc[i][j][q] = 0.f;

    // ---- ldmatrix lane addressing (swizzle-aware) ----
    const int a_row = wm * 64 + (lane & 15);
    const int a_ch  = lane >> 4;
    const int ka    = (a_row >> 1) & 3;   // invariant under +16*mt
    uint32_t aoff[2];
    const int b_k  = (lane & 7) + (((lane >> 3) & 1) << 3);
    const int b_ch = lane >> 4;
    const int bswz = lane & 7;            // = (s*16+b_k)&7
    uint32_t boff[2][4];
    #pragma unroll
    for (int s = 0; s < 2; s++) {
        aoff[s] = (uint32_t)(a_row * 64 + (((s * 2 + a_ch) ^ ka) * 16));
        #pragma unroll
        for (int bt = 0; bt < 4; bt++)
            boff[s][bt] = (uint32_t)((s * 16 + b_k) * 512
                          + (((wn * 8 + bt * 2 + b_ch) ^ bswz) * 16));
    }

    loadT(0); storeT(0);
    __syncthreads();

    for (int kt = 0; kt < NT; kt++) {
        const uint32_t base = smA + (uint32_t)(kt & 1) * STAGE_BYTES;
        if (kt + 1 < NT) loadT(kt + 1);

        #pragma unroll
        for (int s = 0; s < 2; s++) {               // two k16 slabs
            uint32_t ah[4][4];
            #pragma unroll
            for (int mt = 0; mt < 4; mt++)
                ldm_x4(ah[mt], base + A_F16 + aoff[s] + mt * 1024);
            #pragma unroll
            for (int bt = 0; bt < 4; bt++) {        // B fragments on the fly
                uint32_t bh[4];
                ldm_x4_trans(bh, base + B_F16 + boff[s][bt]);
                #pragma unroll
                for (int mt = 0; mt < 4; mt++)
                    #pragma unroll
                    for (int jj = 0; jj < 2; jj++) {
                        const int j = bt * 2 + jj, p = jj * 2;
                        mma_fp16(acc[mt][j], ah[mt], bh[p], bh[p + 1]);
                    }
            }
        }
        if (kt + 1 < NT) storeT((kt + 1) & 1);   // disjoint buffer: overlaps HMMA
        __syncthreads();
    }

    // ---- epilogue straight from fragments ----
    const int col_in = wn * 64 + (lane & 3) * 2;
    #pragma unroll
    for (int mt = 0; mt < 4; mt++) {
        #pragma unroll
        for (int g = 0; g < 2; g++) {
            const int gm = m0 + wm * 64 + mt * 16 + (lane >> 2) + g * 8;
            if (gm >= count) continue;
            const int slot = slots[gm];
            if (MODE == 1) {
                #pragma unroll
                for (int j = 0; j < 8; j++) {
                    const int col = n0 + col_in + j * 8;
                    float2 bb = *(const float2*)(bias + col);
                    float2 o;
                    o.x = fmaxf(acc[mt][j][g * 2 + 0] + bb.x, 0.f);
                    o.y = fmaxf(acc[mt][j][g * 2 + 1] + bb.y, 0.f);
                    *(float2*)&g_h[(size_t)slot * DFFN + col] = o;
                }
            } else {
                const float wgt = g_slot_w[slot];
                #pragma unroll
                for (int j = 0; j < 8; j++) {
                    const int col = n0 + col_in + j * 8;
                    float2 bb = *(const float2*)(bias + col);
                    float2 o;
                    o.x = (acc[mt][j][g * 2 + 0] + bb.x) * wgt;
                    o.y = (acc[mt][j][g * 2 + 1] + bb.y) * wgt;
                    *(float2*)&g_yp[(size_t)slot * DMODEL + col] = o;
                }
            }
        }
    }
}

// ---------------- combine: y[t] = yp[2t] + yp[2t+1] ----------------
__global__ __launch_bounds__(256) void combine_kernel(float* __restrict__ y)
{
    int i = blockIdx.x * blockDim.x + threadIdx.x;
    int t = i >> 8;
    int d4 = i & 255;
    const float4* yp = (const float4*)g_yp;
    float4 a = yp[(size_t)(2 * t) * 256 + d4];
    float4 b = yp[(size_t)(2 * t + 1) * 256 + d4];
    ((float4*)y)[(size_t)t * 256 + d4] =
        make_float4(a.x + b.x, a.y + b.y, a.z + b.z, a.w + b.w);
}

// ---------------- finalize: counts / fraction / aux_loss ----------------
__global__ void finalize_kernel(float* __restrict__ out)
{
    if (threadIdx.x != 0) return;
    const size_t Y = (size_t)NTOK * DMODEL;
    float total = 0.f;
    float c[NEXP];
    #pragma unroll
    for (int e = 0; e < NEXP; e++) { c[e] = (float)g_expert_count[e]; total += c[e]; }
    float denom = fmaxf(total, 1.f);
    float lb = 0.f;
    #pragma unroll
    for (int e = 0; e < NEXP; e++) {
        out[Y + e] = c[e];
        out[Y + NEXP + e] = c[e] / denom;
        float imp = g_imp_sum[e] / (float)NTOK;
        lb += imp * imp;
    }
    float lb_loss = (float)NEXP * lb * 0.01f;
    float z_loss  = (g_z2_sum / (float)NTOK) * 0.001f;
    out[Y + 2 * NEXP] = lb_loss + z_loss;
}

// ---------------- launch ----------------
extern "C" void kernel_launch(void* const* d_in, const int* in_sizes, int n_in,
                              void* d_out, int out_size)
{
    const float* x  = (const float*)d_in[0];
    const float* Wr = (const float*)d_in[1];
    const float* W1 = (const float*)d_in[2];
    const float* b1 = (const float*)d_in[3];
    const float* W2 = (const float*)d_in[4];
    const float* b2 = (const float*)d_in[5];
    float* out = (float*)d_out;

    cudaFuncSetAttribute(moe_gemm_mma<1>,
                         cudaFuncAttributeMaxDynamicSharedMemorySize, SMEM_TOTAL);
    cudaFuncSetAttribute(moe_gemm_mma<2>,
                         cudaFuncAttributeMaxDynamicSharedMemorySize, SMEM_TOTAL);

    zero_kernel<<<1, 32>>>();
    router_kernel<<<NTOK, 128>>>(x, Wr);

    // GEMM1: per-expert M<=8192, N=4096, K=1024 (B = W1[e] in [d][f] layout)
    moe_gemm_mma<1><<<dim3(DFFN / TILE_N, NTOK / TILE_M, NEXP), 256, SMEM_TOTAL>>>(x, W1, b1);
    // GEMM2: per-expert M<=8192, N=1024, K=4096 (B = W2[e] in [f][d] layout)
    moe_gemm_mma<2><<<dim3(DMODEL / TILE_N, NTOK / TILE_M, NEXP), 256, SMEM_TOTAL>>>(nullptr, W2, b2);

    combine_kernel<<<(NTOK * 256) / 256, 256>>>(out);
    finalize_kernel<<<1, 32>>>(out);
}